// round 7
// baseline (speedup 1.0000x reference)
#include <cuda_runtime.h>
#include <cstdint>

// Sinkhorn: B=8, N=2048, eps=0.01, 50 fused (u,v) iterations.
//   u_i = eps*(log_mu - LSE_j((c_ij + v_j)/eps))   (old u cancels)
//   v_j = eps*(log_mu - LSE_i((c_ij + u_i)/eps))   (old v cancels)
// Base-2 domain: x = (c + w) * S, S = 1/(eps*ln2).
// R7: row split across 2 warps (grid 2x), weight vector read directly via
//     LDG (L1-resident, no smem staging), batch-pair serialization for L2
//     residency kept from R6.
// All __device__ scratch referenced from device code only.
// Outputs: [pi (B*N*N), -c (B*N*N), u (B*N), v (B*N)]

#define NN 2048
#define BB 8
#define SINK_S  144.26950408889634f     // 1/(eps*ln2) = 100*log2(e)
#define SINK_C0 -0.07624618986159398f   // eps*log_mu = -0.01*ln(2048)
#define SINK_C1 0.006931471805599453f   // eps*ln2

__device__ float g_u[BB * NN];
__device__ float g_v[BB * NN];
__device__ float g_ct[(size_t)BB * NN * NN];   // c transposed per batch

__device__ __forceinline__ float ex2f(float x) {
    float r; asm("ex2.approx.f32 %0, %1;" : "=f"(r) : "f"(x)); return r;
}
__device__ __forceinline__ float lg2f(float x) {
    float r; asm("lg2.approx.f32 %0, %1;" : "=f"(r) : "f"(x)); return r;
}

__global__ void __launch_bounds__(256) init_kernel() {
    int i = blockIdx.x * 256 + threadIdx.x;
    if (i < BB * NN) g_v[i] = 0.0f;
}

// ---- transpose: g_ct[b][j][i] = c[b][i][j] ----
__global__ void __launch_bounds__(256) transpose_kernel(const float* __restrict__ c) {
    __shared__ float t[32][33];
    const int b = blockIdx.z;
    const size_t base = (size_t)b * NN * NN;
    const int x = blockIdx.x * 32 + threadIdx.x;
    const int y = blockIdx.y * 32 + threadIdx.y;
    #pragma unroll
    for (int j = 0; j < 32; j += 8)
        t[threadIdx.y + j][threadIdx.x] = c[base + (size_t)(y + j) * NN + x];
    __syncthreads();
    const int x2 = blockIdx.y * 32 + threadIdx.x;
    const int y2 = blockIdx.x * 32 + threadIdx.y;
    #pragma unroll
    for (int j = 0; j < 32; j += 8)
        g_ct[base + (size_t)(y2 + j) * NN + x2] = t[threadIdx.x][threadIdx.y + j];
}

// ---- LSE pass. UPASS=true:  mat=c,    vec=g_v, out=g_u.
//                UPASS=false: mat=g_ct, vec=g_u, out=g_v (clamped).
// 2 batches per launch, 1024 CTAs per batch, 2 rows per CTA,
// each row handled by 2 warps (half-row each, 8 float4 per lane).
template <bool UPASS>
__global__ void __launch_bounds__(128, 10) pass_kernel(const float* __restrict__ cmat,
                                                       int b0) {
    __shared__ float sm_m[4], sm_s[4];
    const int b    = b0 + (blockIdx.x >> 10);     // 1024 CTAs per batch
    const int idx  = blockIdx.x & 1023;
    const int row0 = idx * 2;

    const float* vec = UPASS ? g_v : g_u;         // device-side symbol refs only
    const float* mat = UPASS ? cmat : g_ct;
    float*       out = UPASS ? g_u : g_v;

    const int warp = threadIdx.x >> 5, lane = threadIdx.x & 31;
    const int row  = row0 + (warp >> 1);          // warps {0,1}->row0, {2,3}->row0+1
    const int half = warp & 1;                    // half-row: 0 -> [0,256), 1 -> [256,512)
    const int base = lane + half * 256;           // float4 index within row

    const float4* __restrict__ crow =
        reinterpret_cast<const float4*>(mat + ((size_t)b * NN + row) * NN);
    const float4* __restrict__ vv =
        reinterpret_cast<const float4*>(vec + b * NN);

    // Phase 0: front-batched c loads (MLP = 8, streams from L2/DRAM)
    float4 xv[8];
    #pragma unroll
    for (int k = 0; k < 8; k++)
        xv[k] = crow[base + (k << 5)];

    // Phase 1: x = (c + w) * S, per-thread max tree (w loads hit L1)
    float m0 = -1e30f, m1 = -1e30f, m2 = -1e30f, m3 = -1e30f;
    #pragma unroll
    for (int k = 0; k < 8; k++) {
        float4 w = vv[base + (k << 5)];
        xv[k].x = (xv[k].x + w.x) * SINK_S;
        xv[k].y = (xv[k].y + w.y) * SINK_S;
        xv[k].z = (xv[k].z + w.z) * SINK_S;
        xv[k].w = (xv[k].w + w.w) * SINK_S;
        m0 = fmaxf(m0, xv[k].x);
        m1 = fmaxf(m1, xv[k].y);
        m2 = fmaxf(m2, xv[k].z);
        m3 = fmaxf(m3, xv[k].w);
    }
    float m = fmaxf(fmaxf(m0, m1), fmaxf(m2, m3));
    #pragma unroll
    for (int off = 16; off; off >>= 1)
        m = fmaxf(m, __shfl_xor_sync(0xffffffffu, m, off));

    // Phase 2: sum exp2(x - m), 4 independent accumulators
    float s0 = 0.f, s1 = 0.f, s2 = 0.f, s3 = 0.f;
    #pragma unroll
    for (int k = 0; k < 8; k++) {
        s0 += ex2f(xv[k].x - m);
        s1 += ex2f(xv[k].y - m);
        s2 += ex2f(xv[k].z - m);
        s3 += ex2f(xv[k].w - m);
    }
    float s = (s0 + s1) + (s2 + s3);
    #pragma unroll
    for (int off = 16; off; off >>= 1)
        s += __shfl_xor_sync(0xffffffffu, s, off);

    // Cross-warp combine: two half-row (m, s) pairs per row.
    if (lane == 0) { sm_m[warp] = m; sm_s[warp] = s; }
    __syncthreads();

    if (threadIdx.x < 2) {
        const int p = threadIdx.x;                // row pair index within CTA
        float ma = sm_m[2 * p],     sa = sm_s[2 * p];
        float mb = sm_m[2 * p + 1], sb = sm_s[2 * p + 1];
        float mm = fmaxf(ma, mb);
        float ss = fmaf(sa, ex2f(ma - mm), sb * ex2f(mb - mm));
        float r = fmaf(-SINK_C1, mm + lg2f(ss), SINK_C0);
        if (!UPASS && r > 9e8f) r = 0.0f;         // reference clamp on v
        out[b * NN + row0 + p] = r;
    }
}

// ---- epilogue: pi = exp2((c+u+v)*S), -c, u, v ----
__global__ void __launch_bounds__(128) final_kernel(const float* __restrict__ c,
                                                    float* __restrict__ out) {
    const size_t BNN = (size_t)BB * NN * NN;
    const int rowid = blockIdx.x;
    const int b = rowid >> 11;
    const float u = g_u[rowid];
    const float4* __restrict__ crow =
        reinterpret_cast<const float4*>(c + (size_t)rowid * NN);
    const float4* __restrict__ vrow =
        reinterpret_cast<const float4*>(g_v + (size_t)b * NN);
    float4* pio = reinterpret_cast<float4*>(out + (size_t)rowid * NN);
    float4* nco = reinterpret_cast<float4*>(out + BNN + (size_t)rowid * NN);

    #pragma unroll 2
    for (int t = threadIdx.x; t < NN / 4; t += 128) {
        float4 cc = crow[t];
        float4 vv = vrow[t];
        float4 pi, nc;
        pi.x = ex2f(((cc.x + u) + vv.x) * SINK_S);
        pi.y = ex2f(((cc.y + u) + vv.y) * SINK_S);
        pi.z = ex2f(((cc.z + u) + vv.z) * SINK_S);
        pi.w = ex2f(((cc.w + u) + vv.w) * SINK_S);
        nc.x = -cc.x; nc.y = -cc.y; nc.z = -cc.z; nc.w = -cc.w;
        pio[t] = pi;
        nco[t] = nc;
    }
    int gid = blockIdx.x * 128 + threadIdx.x;
    if (gid < BB * NN) {
        out[2 * BNN + gid] = g_u[gid];
        out[2 * BNN + (size_t)BB * NN + gid] = g_v[gid];
    }
}

extern "C" void kernel_launch(void* const* d_in, const int* in_sizes, int n_in,
                              void* d_out, int out_size) {
    const float* c = (const float*)d_in[0];

    init_kernel<<<(BB * NN + 255) / 256, 256>>>();
    transpose_kernel<<<dim3(NN / 32, NN / 32, BB), dim3(32, 8)>>>(c);

    // 4 serialized batch-pairs: per-pass working set ~67MB -> L2-resident.
    for (int pr = 0; pr < 4; ++pr) {
        const int b0 = pr * 2;
        for (int it = 0; it < 50; ++it) {
            pass_kernel<true ><<<2 * 1024, 128>>>(c, b0);   // u-pass
            pass_kernel<false><<<2 * 1024, 128>>>(c, b0);   // v-pass
        }
    }
    final_kernel<<<BB * NN, 128>>>(c, (float*)d_out);
}